// round 2
// baseline (speedup 1.0000x reference)
#include <cuda_runtime.h>
#include <cuda_bf16.h>
#include <math.h>

#define BB 32
#define LL 196
#define DM 512
#define DI 256
#define DS 16
#define M_TOK (BB*LL)   // 6272

// ------------------------ scratch ------------------------
__device__ float g_patches[M_TOK*768];
__device__ float g_t[M_TOK*DM];
__device__ float g_h[M_TOK*DM];
__device__ float g_xz[M_TOK*2*DI];
__device__ float g_xm[M_TOK*DI];
__device__ float g_cat[M_TOK*2*DI];
__device__ float g_xdbl[M_TOK*48];
__device__ float g_dt[M_TOK*DI];
__device__ float g_qkv[M_TOK*3*DM];
__device__ float g_o[M_TOK*DM];
__device__ float g_hid[M_TOK*2048];
__device__ float g_tmean[BB*DM];
__device__ float g_pooled[BB*1024];

// ------------------------ im2col for patch conv ------------------------
__global__ void im2col_kernel(const float* __restrict__ x, float* __restrict__ out){
    int idx = blockIdx.x*blockDim.x + threadIdx.x;
    if (idx >= M_TOK*768) return;
    int m = idx / 768, k = idx % 768;
    int b = m / LL, l = m % LL;
    int py = l / 14, px = l % 14;
    int c = k / 256, r = k % 256;
    int i = r / 16, j = r % 16;
    out[idx] = x[(((size_t)b*3 + c)*224 + py*16 + i)*224 + px*16 + j];
}

// ------------------------ generic SGEMM: C = A[M,K] @ W[N,K]^T (+bias)(+act)(+res) ---
// act: 0 none, 1 softplus, 2 gelu(tanh)
// Requires: K % 16 == 0, lda % 4 == 0, base pointers 16B-aligned.
__global__ void sgemm_kernel(const float* __restrict__ A, int lda,
                             const float* __restrict__ W,
                             const float* __restrict__ bias,
                             const float* __restrict__ res, int ldres,
                             float* __restrict__ C, int ldc,
                             int M, int N, int K, int act)
{
    __shared__ float As[16][65];
    __shared__ float Bs[16][65];
    int bm = blockIdx.y*64, bn = blockIdx.x*64;
    int tx = threadIdx.x & 15, ty = threadIdx.x >> 4;
    float acc[4][4];
    #pragma unroll
    for (int i=0;i<4;i++)
        #pragma unroll
        for (int j=0;j<4;j++) acc[i][j]=0.f;

    // float4 staging: thread -> (m = tid>>2, q = (tid&3)*4)
    int lm = threadIdx.x >> 2;
    int lq = (threadIdx.x & 3) * 4;
    int arow = bm + lm;
    int wrow = bn + lm;

    for (int k0=0;k0<K;k0+=16){
        float4 av = make_float4(0.f,0.f,0.f,0.f);
        float4 wv = make_float4(0.f,0.f,0.f,0.f);
        if (arow < M) av = *(const float4*)&A[(size_t)arow*lda + k0 + lq];
        if (wrow < N) wv = *(const float4*)&W[(size_t)wrow*K   + k0 + lq];
        As[lq+0][lm]=av.x; As[lq+1][lm]=av.y; As[lq+2][lm]=av.z; As[lq+3][lm]=av.w;
        Bs[lq+0][lm]=wv.x; Bs[lq+1][lm]=wv.y; Bs[lq+2][lm]=wv.z; Bs[lq+3][lm]=wv.w;
        __syncthreads();
        #pragma unroll
        for (int kk=0;kk<16;kk++){
            float a[4], bv[4];
            #pragma unroll
            for (int i=0;i<4;i++) a[i] = As[kk][ty + 16*i];
            #pragma unroll
            for (int j=0;j<4;j++) bv[j] = Bs[kk][tx + 16*j];
            #pragma unroll
            for (int i=0;i<4;i++)
                #pragma unroll
                for (int j=0;j<4;j++) acc[i][j] += a[i]*bv[j];
        }
        __syncthreads();
    }
    #pragma unroll
    for (int i=0;i<4;i++){
        int row = bm + ty + 16*i;
        if (row >= M) continue;
        #pragma unroll
        for (int j=0;j<4;j++){
            int col = bn + tx + 16*j;
            if (col >= N) continue;
            float v = acc[i][j];
            if (bias) v += bias[col];
            if (act == 1){
                v = (v > 20.f) ? v : log1pf(expf(v));
            } else if (act == 2){
                float u = v;
                float t = tanhf(0.7978845608f*(u + 0.044715f*u*u*u));
                v = 0.5f*u*(1.f + t);
            }
            if (res) v += res[(size_t)row*ldres + col];
            C[(size_t)row*ldc + col] = v;
        }
    }
}

// ------------------------ LayerNorm ------------------------
__global__ void ln_kernel(const float* __restrict__ x, const float* __restrict__ g,
                          const float* __restrict__ be, float* __restrict__ y){
    int m = blockIdx.x;
    const float* row = x + (size_t)m*DM;
    float s = 0.f, ss = 0.f;
    for (int c = threadIdx.x; c < DM; c += 256){ float v = row[c]; s += v; ss += v*v; }
    #pragma unroll
    for (int off=16;off;off>>=1){ s += __shfl_xor_sync(~0u,s,off); ss += __shfl_xor_sync(~0u,ss,off); }
    __shared__ float sh[16];
    __shared__ float stat[2];
    int wid = threadIdx.x >> 5, lid = threadIdx.x & 31;
    if (lid == 0){ sh[wid] = s; sh[wid+8] = ss; }
    __syncthreads();
    if (threadIdx.x == 0){
        float ts=0.f, tss=0.f;
        for (int w=0;w<8;w++){ ts += sh[w]; tss += sh[w+8]; }
        float mean = ts * (1.f/DM);
        float var  = tss * (1.f/DM) - mean*mean;
        stat[0] = mean;
        stat[1] = rsqrtf(var + 1e-6f);
    }
    __syncthreads();
    float mean = stat[0], rstd = stat[1];
    for (int c = threadIdx.x; c < DM; c += 256){
        y[(size_t)m*DM + c] = (row[c] - mean)*rstd*g[c] + be[c];
    }
}

// ------------------------ causal depthwise conv (k=4) + SiLU ------------------------
__global__ void conv_silu_kernel(const float* __restrict__ xz,
                                 const float* __restrict__ wx, const float* __restrict__ bx,
                                 const float* __restrict__ wz, const float* __restrict__ bz,
                                 float* __restrict__ xm, float* __restrict__ cat){
    int idx = blockIdx.x*blockDim.x + threadIdx.x;
    if (idx >= M_TOK*512) return;
    int m = idx >> 9, c = idx & 511;
    int b = m / LL, l = m % LL;
    bool isx = (c < 256);
    int ci = isx ? c : c - 256;
    const float* w = isx ? (wx + ci*4) : (wz + ci*4);
    float s = isx ? bx[ci] : bz[ci];
    #pragma unroll
    for (int k=0;k<4;k++){
        int ls = l - 3 + k;
        if (ls >= 0) s += w[k] * xz[((size_t)(b*LL + ls))*512 + c];
    }
    float v = s / (1.f + expf(-s));   // silu
    if (isx) xm[(size_t)m*256 + ci] = v;
    else     cat[(size_t)m*512 + c]  = v;
}

// ------------------------ selective scan ------------------------
// one 16-lane group per (b,d); lane = state index n
__global__ void scan_kernel(const float* __restrict__ dt, const float* __restrict__ xdbl,
                            const float* __restrict__ xm, const float* __restrict__ A_log,
                            const float* __restrict__ Dp, float* __restrict__ cat){
    int gid = blockIdx.x*blockDim.x + threadIdx.x;
    int pair = gid >> 4, n = gid & 15;
    int b = pair >> 8, d = pair & 255;
    float A = -expf(A_log[d*16 + n]);
    float Dval = Dp[d];
    float hst = 0.f;
    int base = b*LL;
    for (int l=0;l<LL;l++){
        int m = base + l;
        float dtv = dt[(size_t)m*256 + d];
        float u   = xm[(size_t)m*256 + d];
        float Bv  = xdbl[(size_t)m*48 + 16 + n];
        float Cv  = xdbl[(size_t)m*48 + 32 + n];
        hst = expf(dtv*A)*hst + (dtv*u)*Bv;
        float y = hst*Cv;
        #pragma unroll
        for (int off=8;off;off>>=1) y += __shfl_xor_sync(~0u, y, off);
        if (n == 0) cat[(size_t)m*512 + d] = y + Dval*u;
    }
}

// ------------------------ attention: block per (b,h) ------------------------
__global__ void attn_kernel(const float* __restrict__ qkv, float* __restrict__ o){
    extern __shared__ float smem[];
    float* Ks = smem;
    float* Vs = smem + LL*64;
    int bh = blockIdx.x; int b = bh >> 3, h = bh & 7;
    for (int idx = threadIdx.x; idx < LL*64; idx += blockDim.x){
        int l = idx >> 6, dd = idx & 63;
        const float* p = qkv + (size_t)(b*LL + l)*1536 + h*64 + dd;
        Ks[idx] = p[512];
        Vs[idx] = p[1024];
    }
    __syncthreads();
    int l = threadIdx.x;
    if (l < LL){
        float q[64];
        const float* qp = qkv + (size_t)(b*LL + l)*1536 + h*64;
        #pragma unroll
        for (int dd=0;dd<64;dd++) q[dd] = qp[dd];
        float sc[LL];
        float mx = -1e30f;
        for (int j=0;j<LL;j++){
            float s = 0.f;
            #pragma unroll
            for (int dd=0;dd<64;dd++) s += q[dd]*Ks[j*64+dd];
            s *= 0.125f;
            sc[j] = s;
            mx = fmaxf(mx, s);
        }
        float sum = 0.f;
        for (int j=0;j<LL;j++){ float e = expf(sc[j]-mx); sc[j] = e; sum += e; }
        float inv = 1.f/sum;
        float oa[64];
        #pragma unroll
        for (int dd=0;dd<64;dd++) oa[dd] = 0.f;
        for (int j=0;j<LL;j++){
            float w = sc[j]*inv;
            #pragma unroll
            for (int dd=0;dd<64;dd++) oa[dd] += w*Vs[j*64+dd];
        }
        float* op = o + (size_t)(b*LL + l)*512 + h*64;
        #pragma unroll
        for (int dd=0;dd<64;dd++) op[dd] = oa[dd];
    }
}

// ------------------------ mean over L ------------------------
__global__ void pool_kernel(const float* __restrict__ t, float* __restrict__ tmean){
    int idx = blockIdx.x*blockDim.x + threadIdx.x;
    if (idx >= BB*DM) return;
    int b = idx / DM, c = idx % DM;
    const float* p = t + (size_t)b*LL*DM + c;
    float s = 0.f;
    for (int l=0;l<LL;l++) s += p[(size_t)l*DM];
    tmean[idx] = s * (1.f/LL);
}

// ------------------------ final fc ------------------------
__global__ void fc_kernel(const float* __restrict__ pooled, const float* __restrict__ fw,
                          const float* __restrict__ fb, float* __restrict__ out){
    int i = threadIdx.x; // 0..127
    int b = i >> 2, oi = i & 3;
    float s = fb[oi];
    const float* pp = pooled + b*1024;
    const float* wp = fw + oi*1024;
    for (int k=0;k<1024;k++) s += pp[k]*wp[k];
    out[b*4 + oi] = s;
}

// ------------------------ host ------------------------
static void gemm(const float* A, int lda, const float* W, const float* bias,
                 const float* res, int ldres, float* C, int ldc,
                 int M, int N, int K, int act){
    dim3 grid((N+63)/64, (M+63)/64);
    sgemm_kernel<<<grid, 256>>>(A, lda, W, bias, res, ldres, C, ldc, M, N, K, act);
}

extern "C" void kernel_launch(void* const* d_in, const int* in_sizes, int n_in,
                              void* d_out, int out_size)
{
    const float* x          = (const float*)d_in[0];
    const float* patch_w    = (const float*)d_in[1];
    const float* patch_b    = (const float*)d_in[2];
    const float* ln1_g      = (const float*)d_in[3];
    const float* ln1_b      = (const float*)d_in[4];
    const float* in_proj_w  = (const float*)d_in[5];
    const float* convx_w    = (const float*)d_in[6];
    const float* convx_b    = (const float*)d_in[7];
    const float* convz_w    = (const float*)d_in[8];
    const float* convz_b    = (const float*)d_in[9];
    const float* x_proj_w   = (const float*)d_in[10];
    const float* dt_proj_w  = (const float*)d_in[11];
    const float* dt_proj_b  = (const float*)d_in[12];
    const float* A_log      = (const float*)d_in[13];
    const float* Dp         = (const float*)d_in[14];
    const float* out_proj_w = (const float*)d_in[15];
    const float* ln2_g      = (const float*)d_in[16];
    const float* ln2_b      = (const float*)d_in[17];
    const float* qkv_w      = (const float*)d_in[18];
    const float* attn_proj_w= (const float*)d_in[19];
    const float* ln3_g      = (const float*)d_in[20];
    const float* ln3_b      = (const float*)d_in[21];
    const float* mlp_w1     = (const float*)d_in[22];
    const float* mlp_b1     = (const float*)d_in[23];
    const float* mlp_w2     = (const float*)d_in[24];
    const float* mlp_b2     = (const float*)d_in[25];
    const float* head_w     = (const float*)d_in[26];
    const float* head_b     = (const float*)d_in[27];
    const float* fc_w       = (const float*)d_in[28];
    const float* fc_b       = (const float*)d_in[29];
    float* out = (float*)d_out;

    float *patches,*t,*h,*xz,*xm,*cat,*xdbl,*dtb,*qkv,*o,*hid,*tmean,*pooled;
    cudaGetSymbolAddress((void**)&patches, g_patches);
    cudaGetSymbolAddress((void**)&t,       g_t);
    cudaGetSymbolAddress((void**)&h,       g_h);
    cudaGetSymbolAddress((void**)&xz,      g_xz);
    cudaGetSymbolAddress((void**)&xm,      g_xm);
    cudaGetSymbolAddress((void**)&cat,     g_cat);
    cudaGetSymbolAddress((void**)&xdbl,    g_xdbl);
    cudaGetSymbolAddress((void**)&dtb,     g_dt);
    cudaGetSymbolAddress((void**)&qkv,     g_qkv);
    cudaGetSymbolAddress((void**)&o,       g_o);
    cudaGetSymbolAddress((void**)&hid,     g_hid);
    cudaGetSymbolAddress((void**)&tmean,   g_tmean);
    cudaGetSymbolAddress((void**)&pooled,  g_pooled);

    // 1. patch embed
    im2col_kernel<<<(M_TOK*768 + 255)/256, 256>>>(x, patches);
    gemm(patches, 768, patch_w, patch_b, nullptr, 0, t, 512, M_TOK, 512, 768, 0);
    // 2. mamba branch
    ln_kernel<<<M_TOK, 256>>>(t, ln1_g, ln1_b, h);
    gemm(h, 512, in_proj_w, nullptr, nullptr, 0, xz, 512, M_TOK, 512, 512, 0);
    conv_silu_kernel<<<(M_TOK*512 + 255)/256, 256>>>(xz, convx_w, convx_b, convz_w, convz_b, xm, cat);
    gemm(xm, 256, x_proj_w, nullptr, nullptr, 0, xdbl, 48, M_TOK, 48, 256, 0);
    gemm(xdbl, 48, dt_proj_w, dt_proj_b, nullptr, 0, dtb, 256, M_TOK, 256, 16, 1);
    scan_kernel<<<512, 256>>>(dtb, xdbl, xm, A_log, Dp, cat);
    gemm(cat, 512, out_proj_w, nullptr, t, 512, t, 512, M_TOK, 512, 512, 0);
    // 3. attention
    ln_kernel<<<M_TOK, 256>>>(t, ln2_g, ln2_b, h);
    gemm(h, 512, qkv_w, nullptr, nullptr, 0, qkv, 1536, M_TOK, 1536, 512, 0);
    cudaFuncSetAttribute(attn_kernel, cudaFuncAttributeMaxDynamicSharedMemorySize, 2*LL*64*4);
    attn_kernel<<<BB*8, 256, 2*LL*64*4>>>(qkv, o);
    gemm(o, 512, attn_proj_w, nullptr, t, 512, t, 512, M_TOK, 512, 512, 0);
    // 4. MLP
    ln_kernel<<<M_TOK, 256>>>(t, ln3_g, ln3_b, h);
    gemm(h, 512, mlp_w1, mlp_b1, nullptr, 0, hid, 2048, M_TOK, 2048, 512, 2);
    gemm(hid, 2048, mlp_w2, mlp_b2, t, 512, t, 512, M_TOK, 512, 2048, 0);
    // 5. head (pool first: mean_L(t @ W^T + b) == mean_L(t) @ W^T + b)
    pool_kernel<<<(BB*DM + 255)/256, 256>>>(t, tmean);
    gemm(tmean, 512, head_w, head_b, nullptr, 0, pooled, 1024, BB, 1024, 512, 0);
    fc_kernel<<<1, 128>>>(pooled, fc_w, fc_b, out);
}

// round 3
// speedup vs baseline: 2.5641x; 2.5641x over previous
#include <cuda_runtime.h>
#include <cuda_bf16.h>
#include <math.h>

#define BB 32
#define LL 196
#define DM 512
#define DI 256
#define DS 16
#define M_TOK (BB*LL)   // 6272

// ------------------------ scratch ------------------------
__device__ float g_patches[M_TOK*768];
__device__ float g_t[M_TOK*DM];
__device__ float g_h[M_TOK*DM];
__device__ float g_xz[M_TOK*2*DI];
__device__ float g_xm[M_TOK*DI];
__device__ float g_cat[M_TOK*2*DI];
__device__ float g_xdbl[M_TOK*48];
__device__ float g_dt[M_TOK*DI];
__device__ float g_qkv[M_TOK*3*DM];
__device__ float g_o[M_TOK*DM];
__device__ float g_hid[M_TOK*2048];
__device__ float g_tmean[BB*DM];
__device__ float g_pooled[BB*1024];

__device__ __forceinline__ unsigned f2tf32(float f){
    unsigned r;
    asm("cvt.rna.tf32.f32 %0, %1;" : "=r"(r) : "f"(f));
    return r;
}

// ------------------------ im2col for patch conv ------------------------
__global__ void im2col_kernel(const float* __restrict__ x, float* __restrict__ out){
    int idx = blockIdx.x*blockDim.x + threadIdx.x;
    if (idx >= M_TOK*768) return;
    int m = idx / 768, k = idx % 768;
    int b = m / LL, l = m % LL;
    int py = l / 14, px = l % 14;
    int c = k / 256, r = k % 256;
    int i = r / 16, j = r % 16;
    out[idx] = x[(((size_t)b*3 + c)*224 + py*16 + i)*224 + px*16 + j];
}

// ------------------------ TF32 tensor-core GEMM ------------------------
// C[M,N] = A[M,K] @ W[N,K]^T (+bias)(+act)(+res)
// REQUIRES M%128==0, N%128==0, K%32==0. act: 0 none, 2 gelu.
// Block 128x128, 8 warps (4m x 2n), warp tile 32x64, mma m16n8k8 tf32.
#define LDS_S 36  // smem row stride (words): (4*gid+tig) -> conflict-free
__global__ void __launch_bounds__(256) tgemm_kernel(
        const float* __restrict__ A, int lda,
        const float* __restrict__ W,
        const float* __restrict__ bias,
        const float* __restrict__ res, int ldres,
        float* __restrict__ C, int ldc,
        int M, int N, int K, int act)
{
    __shared__ unsigned As[128*LDS_S];
    __shared__ unsigned Ws[128*LDS_S];
    int bm = blockIdx.y*128, bn = blockIdx.x*128;
    int tid = threadIdx.x;
    int warp = tid >> 5, lane = tid & 31;
    int wm = (warp >> 1) * 32;   // warp m-offset (0,32,64,96)
    int wn = (warp & 1) * 64;    // warp n-offset (0,64)
    int gid = lane >> 2, tig = lane & 3;

    float c[2][8][4];
    #pragma unroll
    for (int mi=0;mi<2;mi++)
        #pragma unroll
        for (int ni=0;ni<8;ni++)
            #pragma unroll
            for (int q=0;q<4;q++) c[mi][ni][q] = 0.f;

    int srow = tid >> 3;           // 0..31 (row within 32-row slab)
    int scol = (tid & 7) * 4;      // 0,4,...,28

    for (int k0=0; k0<K; k0+=32){
        // stage 128x32 of A and W, fp32 -> tf32
        #pragma unroll
        for (int i=0;i<4;i++){
            int r = srow + i*32;
            float4 av = *(const float4*)&A[(size_t)(bm+r)*lda + k0 + scol];
            float4 wv = *(const float4*)&W[(size_t)(bn+r)*K   + k0 + scol];
            uint4 at, wt;
            at.x=f2tf32(av.x); at.y=f2tf32(av.y); at.z=f2tf32(av.z); at.w=f2tf32(av.w);
            wt.x=f2tf32(wv.x); wt.y=f2tf32(wv.y); wt.z=f2tf32(wv.z); wt.w=f2tf32(wv.w);
            *(uint4*)&As[r*LDS_S + scol] = at;
            *(uint4*)&Ws[r*LDS_S + scol] = wt;
        }
        __syncthreads();
        #pragma unroll
        for (int kk=0;kk<4;kk++){
            int kb = kk*8;
            unsigned a[2][4], b[8][2];
            #pragma unroll
            for (int mi=0;mi<2;mi++){
                int r0 = wm + mi*16 + gid;
                a[mi][0] = As[r0*LDS_S     + kb + tig];
                a[mi][1] = As[(r0+8)*LDS_S + kb + tig];
                a[mi][2] = As[r0*LDS_S     + kb + tig + 4];
                a[mi][3] = As[(r0+8)*LDS_S + kb + tig + 4];
            }
            #pragma unroll
            for (int ni=0;ni<8;ni++){
                int n0 = wn + ni*8 + gid;
                b[ni][0] = Ws[n0*LDS_S + kb + tig];
                b[ni][1] = Ws[n0*LDS_S + kb + tig + 4];
            }
            #pragma unroll
            for (int mi=0;mi<2;mi++)
                #pragma unroll
                for (int ni=0;ni<8;ni++){
                    asm volatile(
                        "mma.sync.aligned.m16n8k8.row.col.f32.tf32.tf32.f32 "
                        "{%0,%1,%2,%3}, {%4,%5,%6,%7}, {%8,%9}, {%0,%1,%2,%3};"
                        : "+f"(c[mi][ni][0]), "+f"(c[mi][ni][1]),
                          "+f"(c[mi][ni][2]), "+f"(c[mi][ni][3])
                        : "r"(a[mi][0]), "r"(a[mi][1]), "r"(a[mi][2]), "r"(a[mi][3]),
                          "r"(b[ni][0]), "r"(b[ni][1]));
                }
        }
        __syncthreads();
    }

    // epilogue
    #pragma unroll
    for (int mi=0;mi<2;mi++){
        #pragma unroll
        for (int ni=0;ni<8;ni++){
            int col = bn + wn + ni*8 + 2*tig;
            #pragma unroll
            for (int half=0; half<2; half++){
                int row = bm + wm + mi*16 + gid + half*8;
                float v0 = c[mi][ni][half*2+0];
                float v1 = c[mi][ni][half*2+1];
                if (bias){ v0 += bias[col]; v1 += bias[col+1]; }
                if (act == 2){
                    float u = v0, t = tanhf(0.7978845608f*(u + 0.044715f*u*u*u));
                    v0 = 0.5f*u*(1.f + t);
                    u = v1; t = tanhf(0.7978845608f*(u + 0.044715f*u*u*u));
                    v1 = 0.5f*u*(1.f + t);
                }
                if (res){
                    v0 += res[(size_t)row*ldres + col];
                    v1 += res[(size_t)row*ldres + col+1];
                }
                *(float2*)&C[(size_t)row*ldc + col] = make_float2(v0, v1);
            }
        }
    }
}

// ------------------------ fallback scalar SGEMM (small/odd shapes) ------
// act: 0 none, 1 softplus, 2 gelu. Requires K%16==0.
__global__ void sgemm_kernel(const float* __restrict__ A, int lda,
                             const float* __restrict__ W,
                             const float* __restrict__ bias,
                             const float* __restrict__ res, int ldres,
                             float* __restrict__ C, int ldc,
                             int M, int N, int K, int act)
{
    __shared__ float As[16][65];
    __shared__ float Bs[16][65];
    int bm = blockIdx.y*64, bn = blockIdx.x*64;
    int tx = threadIdx.x & 15, ty = threadIdx.x >> 4;
    float acc[4][4];
    #pragma unroll
    for (int i=0;i<4;i++)
        #pragma unroll
        for (int j=0;j<4;j++) acc[i][j]=0.f;

    int lm = threadIdx.x >> 2;
    int lq = (threadIdx.x & 3) * 4;
    int arow = bm + lm;
    int wrow = bn + lm;

    for (int k0=0;k0<K;k0+=16){
        float4 av = make_float4(0.f,0.f,0.f,0.f);
        float4 wv = make_float4(0.f,0.f,0.f,0.f);
        if (arow < M) av = *(const float4*)&A[(size_t)arow*lda + k0 + lq];
        if (wrow < N) wv = *(const float4*)&W[(size_t)wrow*K   + k0 + lq];
        As[lq+0][lm]=av.x; As[lq+1][lm]=av.y; As[lq+2][lm]=av.z; As[lq+3][lm]=av.w;
        Bs[lq+0][lm]=wv.x; Bs[lq+1][lm]=wv.y; Bs[lq+2][lm]=wv.z; Bs[lq+3][lm]=wv.w;
        __syncthreads();
        #pragma unroll
        for (int kk=0;kk<16;kk++){
            float a[4], bv[4];
            #pragma unroll
            for (int i=0;i<4;i++) a[i] = As[kk][ty + 16*i];
            #pragma unroll
            for (int j=0;j<4;j++) bv[j] = Bs[kk][tx + 16*j];
            #pragma unroll
            for (int i=0;i<4;i++)
                #pragma unroll
                for (int j=0;j<4;j++) acc[i][j] += a[i]*bv[j];
        }
        __syncthreads();
    }
    #pragma unroll
    for (int i=0;i<4;i++){
        int row = bm + ty + 16*i;
        if (row >= M) continue;
        #pragma unroll
        for (int j=0;j<4;j++){
            int col = bn + tx + 16*j;
            if (col >= N) continue;
            float v = acc[i][j];
            if (bias) v += bias[col];
            if (act == 1){
                v = (v > 20.f) ? v : log1pf(expf(v));
            } else if (act == 2){
                float u = v;
                float t = tanhf(0.7978845608f*(u + 0.044715f*u*u*u));
                v = 0.5f*u*(1.f + t);
            }
            if (res) v += res[(size_t)row*ldres + col];
            C[(size_t)row*ldc + col] = v;
        }
    }
}

// ------------------------ LayerNorm ------------------------
__global__ void ln_kernel(const float* __restrict__ x, const float* __restrict__ g,
                          const float* __restrict__ be, float* __restrict__ y){
    int m = blockIdx.x;
    const float* row = x + (size_t)m*DM;
    float s = 0.f, ss = 0.f;
    for (int c = threadIdx.x; c < DM; c += 256){ float v = row[c]; s += v; ss += v*v; }
    #pragma unroll
    for (int off=16;off;off>>=1){ s += __shfl_xor_sync(~0u,s,off); ss += __shfl_xor_sync(~0u,ss,off); }
    __shared__ float sh[16];
    __shared__ float stat[2];
    int wid = threadIdx.x >> 5, lid = threadIdx.x & 31;
    if (lid == 0){ sh[wid] = s; sh[wid+8] = ss; }
    __syncthreads();
    if (threadIdx.x == 0){
        float ts=0.f, tss=0.f;
        for (int w=0;w<8;w++){ ts += sh[w]; tss += sh[w+8]; }
        float mean = ts * (1.f/DM);
        float var  = tss * (1.f/DM) - mean*mean;
        stat[0] = mean;
        stat[1] = rsqrtf(var + 1e-6f);
    }
    __syncthreads();
    float mean = stat[0], rstd = stat[1];
    for (int c = threadIdx.x; c < DM; c += 256){
        y[(size_t)m*DM + c] = (row[c] - mean)*rstd*g[c] + be[c];
    }
}

// ------------------------ causal depthwise conv (k=4) + SiLU ------------------------
__global__ void conv_silu_kernel(const float* __restrict__ xz,
                                 const float* __restrict__ wx, const float* __restrict__ bx,
                                 const float* __restrict__ wz, const float* __restrict__ bz,
                                 float* __restrict__ xm, float* __restrict__ cat){
    int idx = blockIdx.x*blockDim.x + threadIdx.x;
    if (idx >= M_TOK*512) return;
    int m = idx >> 9, c = idx & 511;
    int b = m / LL, l = m % LL;
    bool isx = (c < 256);
    int ci = isx ? c : c - 256;
    const float* w = isx ? (wx + ci*4) : (wz + ci*4);
    float s = isx ? bx[ci] : bz[ci];
    #pragma unroll
    for (int k=0;k<4;k++){
        int ls = l - 3 + k;
        if (ls >= 0) s += w[k] * xz[((size_t)(b*LL + ls))*512 + c];
    }
    float v = s / (1.f + expf(-s));   // silu
    if (isx) xm[(size_t)m*256 + ci] = v;
    else     cat[(size_t)m*512 + c]  = v;
}

// ------------------------ selective scan ------------------------
__global__ void scan_kernel(const float* __restrict__ dt, const float* __restrict__ xdbl,
                            const float* __restrict__ xm, const float* __restrict__ A_log,
                            const float* __restrict__ Dp, float* __restrict__ cat){
    int gid = blockIdx.x*blockDim.x + threadIdx.x;
    int pair = gid >> 4, n = gid & 15;
    int b = pair >> 8, d = pair & 255;
    float A = -expf(A_log[d*16 + n]);
    float Dval = Dp[d];
    float hst = 0.f;
    int base = b*LL;
    for (int l=0;l<LL;l++){
        int m = base + l;
        float dtv = dt[(size_t)m*256 + d];
        float u   = xm[(size_t)m*256 + d];
        float Bv  = xdbl[(size_t)m*48 + 16 + n];
        float Cv  = xdbl[(size_t)m*48 + 32 + n];
        hst = expf(dtv*A)*hst + (dtv*u)*Bv;
        float y = hst*Cv;
        #pragma unroll
        for (int off=8;off;off>>=1) y += __shfl_xor_sync(~0u, y, off);
        if (n == 0) cat[(size_t)m*512 + d] = y + Dval*u;
    }
}

// ------------------------ attention: block per (b,h) ------------------------
__global__ void attn_kernel(const float* __restrict__ qkv, float* __restrict__ o){
    extern __shared__ float smem[];
    float* Ks = smem;
    float* Vs = smem + LL*64;
    int bh = blockIdx.x; int b = bh >> 3, h = bh & 7;
    for (int idx = threadIdx.x; idx < LL*64; idx += blockDim.x){
        int l = idx >> 6, dd = idx & 63;
        const float* p = qkv + (size_t)(b*LL + l)*1536 + h*64 + dd;
        Ks[idx] = p[512];
        Vs[idx] = p[1024];
    }
    __syncthreads();
    int l = threadIdx.x;
    if (l < LL){
        float q[64];
        const float* qp = qkv + (size_t)(b*LL + l)*1536 + h*64;
        #pragma unroll
        for (int dd=0;dd<64;dd++) q[dd] = qp[dd];
        float sc[LL];
        float mx = -1e30f;
        for (int j=0;j<LL;j++){
            float s = 0.f;
            #pragma unroll
            for (int dd=0;dd<64;dd++) s += q[dd]*Ks[j*64+dd];
            s *= 0.125f;
            sc[j] = s;
            mx = fmaxf(mx, s);
        }
        float sum = 0.f;
        for (int j=0;j<LL;j++){ float e = expf(sc[j]-mx); sc[j] = e; sum += e; }
        float inv = 1.f/sum;
        float oa[64];
        #pragma unroll
        for (int dd=0;dd<64;dd++) oa[dd] = 0.f;
        for (int j=0;j<LL;j++){
            float w = sc[j]*inv;
            #pragma unroll
            for (int dd=0;dd<64;dd++) oa[dd] += w*Vs[j*64+dd];
        }
        float* op = o + (size_t)(b*LL + l)*512 + h*64;
        #pragma unroll
        for (int dd=0;dd<64;dd++) op[dd] = oa[dd];
    }
}

// ------------------------ mean over L ------------------------
__global__ void pool_kernel(const float* __restrict__ t, float* __restrict__ tmean){
    int idx = blockIdx.x*blockDim.x + threadIdx.x;
    if (idx >= BB*DM) return;
    int b = idx / DM, c = idx % DM;
    const float* p = t + (size_t)b*LL*DM + c;
    float s = 0.f;
    for (int l=0;l<LL;l++) s += p[(size_t)l*DM];
    tmean[idx] = s * (1.f/LL);
}

// ------------------------ final fc ------------------------
__global__ void fc_kernel(const float* __restrict__ pooled, const float* __restrict__ fw,
                          const float* __restrict__ fb, float* __restrict__ out){
    int i = threadIdx.x; // 0..127
    int b = i >> 2, oi = i & 3;
    float s = fb[oi];
    const float* pp = pooled + b*1024;
    const float* wp = fw + oi*1024;
    for (int k=0;k<1024;k++) s += pp[k]*wp[k];
    out[b*4 + oi] = s;
}

// ------------------------ host ------------------------
static void gemm(const float* A, int lda, const float* W, const float* bias,
                 const float* res, int ldres, float* C, int ldc,
                 int M, int N, int K, int act){
    if ((M % 128) == 0 && (N % 128) == 0 && (K % 32) == 0 && act != 1){
        dim3 grid(N/128, M/128);
        tgemm_kernel<<<grid, 256>>>(A, lda, W, bias, res, ldres, C, ldc, M, N, K, act);
    } else {
        dim3 grid((N+63)/64, (M+63)/64);
        sgemm_kernel<<<grid, 256>>>(A, lda, W, bias, res, ldres, C, ldc, M, N, K, act);
    }
}

extern "C" void kernel_launch(void* const* d_in, const int* in_sizes, int n_in,
                              void* d_out, int out_size)
{
    const float* x          = (const float*)d_in[0];
    const float* patch_w    = (const float*)d_in[1];
    const float* patch_b    = (const float*)d_in[2];
    const float* ln1_g      = (const float*)d_in[3];
    const float* ln1_b      = (const float*)d_in[4];
    const float* in_proj_w  = (const float*)d_in[5];
    const float* convx_w    = (const float*)d_in[6];
    const float* convx_b    = (const float*)d_in[7];
    const float* convz_w    = (const float*)d_in[8];
    const float* convz_b    = (const float*)d_in[9];
    const float* x_proj_w   = (const float*)d_in[10];
    const float* dt_proj_w  = (const float*)d_in[11];
    const float* dt_proj_b  = (const float*)d_in[12];
    const float* A_log      = (const float*)d_in[13];
    const float* Dp         = (const float*)d_in[14];
    const float* out_proj_w = (const float*)d_in[15];
    const float* ln2_g      = (const float*)d_in[16];
    const float* ln2_b      = (const float*)d_in[17];
    const float* qkv_w      = (const float*)d_in[18];
    const float* attn_proj_w= (const float*)d_in[19];
    const float* ln3_g      = (const float*)d_in[20];
    const float* ln3_b      = (const float*)d_in[21];
    const float* mlp_w1     = (const float*)d_in[22];
    const float* mlp_b1     = (const float*)d_in[23];
    const float* mlp_w2     = (const float*)d_in[24];
    const float* mlp_b2     = (const float*)d_in[25];
    const float* head_w     = (const float*)d_in[26];
    const float* head_b     = (const float*)d_in[27];
    const float* fc_w       = (const float*)d_in[28];
    const float* fc_b       = (const float*)d_in[29];
    float* out = (float*)d_out;

    float *patches,*t,*h,*xz,*xm,*cat,*xdbl,*dtb,*qkv,*o,*hid,*tmean,*pooled;
    cudaGetSymbolAddress((void**)&patches, g_patches);
    cudaGetSymbolAddress((void**)&t,       g_t);
    cudaGetSymbolAddress((void**)&h,       g_h);
    cudaGetSymbolAddress((void**)&xz,      g_xz);
    cudaGetSymbolAddress((void**)&xm,      g_xm);
    cudaGetSymbolAddress((void**)&cat,     g_cat);
    cudaGetSymbolAddress((void**)&xdbl,    g_xdbl);
    cudaGetSymbolAddress((void**)&dtb,     g_dt);
    cudaGetSymbolAddress((void**)&qkv,     g_qkv);
    cudaGetSymbolAddress((void**)&o,       g_o);
    cudaGetSymbolAddress((void**)&hid,     g_hid);
    cudaGetSymbolAddress((void**)&tmean,   g_tmean);
    cudaGetSymbolAddress((void**)&pooled,  g_pooled);

    // 1. patch embed
    im2col_kernel<<<(M_TOK*768 + 255)/256, 256>>>(x, patches);
    gemm(patches, 768, patch_w, patch_b, nullptr, 0, t, 512, M_TOK, 512, 768, 0);
    // 2. mamba branch
    ln_kernel<<<M_TOK, 256>>>(t, ln1_g, ln1_b, h);
    gemm(h, 512, in_proj_w, nullptr, nullptr, 0, xz, 512, M_TOK, 512, 512, 0);
    conv_silu_kernel<<<(M_TOK*512 + 255)/256, 256>>>(xz, convx_w, convx_b, convz_w, convz_b, xm, cat);
    gemm(xm, 256, x_proj_w, nullptr, nullptr, 0, xdbl, 48, M_TOK, 48, 256, 0);
    gemm(xdbl, 48, dt_proj_w, dt_proj_b, nullptr, 0, dtb, 256, M_TOK, 256, 16, 1);
    scan_kernel<<<512, 256>>>(dtb, xdbl, xm, A_log, Dp, cat);
    gemm(cat, 512, out_proj_w, nullptr, t, 512, t, 512, M_TOK, 512, 512, 0);
    // 3. attention
    ln_kernel<<<M_TOK, 256>>>(t, ln2_g, ln2_b, h);
    gemm(h, 512, qkv_w, nullptr, nullptr, 0, qkv, 1536, M_TOK, 1536, 512, 0);
    cudaFuncSetAttribute(attn_kernel, cudaFuncAttributeMaxDynamicSharedMemorySize, 2*LL*64*4);
    attn_kernel<<<BB*8, 256, 2*LL*64*4>>>(qkv, o);
    gemm(o, 512, attn_proj_w, nullptr, t, 512, t, 512, M_TOK, 512, 512, 0);
    // 4. MLP
    ln_kernel<<<M_TOK, 256>>>(t, ln3_g, ln3_b, h);
    gemm(h, 512, mlp_w1, mlp_b1, nullptr, 0, hid, 2048, M_TOK, 2048, 512, 2);
    gemm(hid, 2048, mlp_w2, mlp_b2, t, 512, t, 512, M_TOK, 512, 2048, 0);
    // 5. head (pool first: mean_L(t @ W^T + b) == mean_L(t) @ W^T + b)
    pool_kernel<<<(BB*DM + 255)/256, 256>>>(t, tmean);
    gemm(tmean, 512, head_w, head_b, nullptr, 0, pooled, 1024, BB, 1024, 512, 0);
    fc_kernel<<<1, 128>>>(pooled, fc_w, fc_b, out);
}